// round 3
// baseline (speedup 1.0000x reference)
#include <cuda_runtime.h>
#include <stdint.h>
#include <math.h>

typedef unsigned long long ull;

#define Hh 50
#define Ww 76
#define PP 3800
#define CC 512
#define NIMG 8
#define NANCH 34200
#define NSORT 65536
#define PRE 6000
#define POST 300
#define NWORD 94

#define LOC_OFF   0
#define SCORE_OFF (NIMG*NANCH*4)
#define ROI_OFF   (SCORE_OFF + NIMG*NANCH*2)
#define ANCH_OFF  (ROI_OFF + NIMG*POST*4)

__device__ float g_feat[(size_t)NIMG*CC*PP];
__device__ float g_wT[9*CC*CC];
__device__ float g_boxes[(size_t)NIMG*NANCH*4];
__device__ float g_fg[NIMG*NANCH];
__device__ ull   g_keys[NIMG*NSORT];
__device__ float g_bsel[NIMG*PRE*4];
__device__ float g_ssel[NIMG*PRE];
__device__ float g_area[NIMG*PRE];
__device__ ull   g_mask[(size_t)NIMG*PRE*NWORD];

__global__ void transpose_w(const float* __restrict__ w){
    int i = blockIdx.x*blockDim.x + threadIdx.x;
    if (i >= 9*CC*CC) return;
    int oc = i & 511, ic = (i >> 9) & 511, kk = i >> 18;
    g_wT[i] = w[(oc*CC + ic)*9 + kk];
}

__global__ __launch_bounds__(256,2) void conv3x3(const float* __restrict__ x,
                                                 const float* __restrict__ bias){
    __shared__ float As[2][16][128];
    __shared__ float Bs[2][16][128];
    __shared__ int   spy[128];
    __shared__ unsigned char sxm[128], sxp[128];

    const int n = blockIdx.z, oc0 = blockIdx.y*128, p0 = blockIdx.x*128;
    const int tid = threadIdx.x, tx = tid & 15, ty = tid >> 4;

    if (tid < 128){
        int p = p0 + tid;
        if (p < PP){
            int y = p / Ww, xx = p - y*Ww;
            spy[tid] = y; sxm[tid] = (xx > 0); sxp[tid] = (xx < Ww-1);
        } else { spy[tid] = -100; sxm[tid] = 0; sxp[tid] = 0; }
    }
    __syncthreads();

    const float* xn = x + (size_t)n*CC*PP;
    const int ak0 = tid >> 5, ak1 = ak0 + 8, ac0 = (tid & 31) << 2;
    const int bk = tid >> 4, pxb = (tid & 15) << 3;

    float acc[8][8];
    #pragma unroll
    for (int i=0;i<8;i++)
        #pragma unroll
        for (int j=0;j<8;j++) acc[i][j] = 0.f;

    float4 ra0, ra1; float rb[8];

#define LOAD_REGS(KC) {                                                         \
        int kk9 = (KC) >> 5; int ic0 = ((KC) & 31) << 4;                        \
        const float* wa = g_wT + ((size_t)(kk9*CC + ic0))*CC + oc0;             \
        ra0 = *(const float4*)(wa + (size_t)ak0*CC + ac0);                      \
        ra1 = *(const float4*)(wa + (size_t)ak1*CC + ac0);                      \
        int dy = kk9/3 - 1; int dx = kk9 - (kk9/3)*3 - 1;                       \
        const float* src = xn + (size_t)(ic0 + bk)*PP + (p0 + dy*Ww + dx);      \
        _Pragma("unroll")                                                       \
        for (int e=0;e<8;e++){                                                  \
            int pxi = pxb + e;                                                  \
            int yy = spy[pxi] + dy;                                             \
            bool v = (yy >= 0) && (yy < Hh) &&                                  \
                     (dx == 0 || (dx < 0 ? (sxm[pxi]!=0) : (sxp[pxi]!=0)));     \
            rb[e] = v ? src[pxi] : 0.f;                                         \
        } }

#define STORE_REGS(BUF) {                                                       \
        *(float4*)&As[BUF][ak0][ac0] = ra0;                                     \
        *(float4*)&As[BUF][ak1][ac0] = ra1;                                     \
        *(float4*)&Bs[BUF][bk][pxb]   = make_float4(rb[0],rb[1],rb[2],rb[3]);   \
        *(float4*)&Bs[BUF][bk][pxb+4] = make_float4(rb[4],rb[5],rb[6],rb[7]); }

    LOAD_REGS(0);
    STORE_REGS(0);
    __syncthreads();

    int cur = 0;
    for (int kc = 0; kc < 288; kc++){
        if (kc < 287) LOAD_REGS(kc+1);
        #pragma unroll
        for (int kk=0; kk<16; kk++){
            float4 a0 = *(const float4*)&As[cur][kk][ty<<3];
            float4 a1 = *(const float4*)&As[cur][kk][(ty<<3)+4];
            float4 b0 = *(const float4*)&Bs[cur][kk][tx<<3];
            float4 b1 = *(const float4*)&Bs[cur][kk][(tx<<3)+4];
            float av[8] = {a0.x,a0.y,a0.z,a0.w,a1.x,a1.y,a1.z,a1.w};
            float bv[8] = {b0.x,b0.y,b0.z,b0.w,b1.x,b1.y,b1.z,b1.w};
            #pragma unroll
            for (int i=0;i<8;i++)
                #pragma unroll
                for (int j=0;j<8;j++) acc[i][j] = fmaf(av[i], bv[j], acc[i][j]);
        }
        if (kc < 287) STORE_REGS(cur^1);
        __syncthreads();
        cur ^= 1;
    }

    #pragma unroll
    for (int i=0;i<8;i++){
        int oc = oc0 + (ty<<3) + i;
        float bs = bias[oc];
        float* dst = g_feat + ((size_t)n*CC + oc)*PP;
        #pragma unroll
        for (int j=0;j<8;j++){
            int p = p0 + (tx<<3) + j;
            if (p < PP) dst[p] = fmaxf(acc[i][j] + bs, 0.f);
        }
    }
#undef LOAD_REGS
#undef STORE_REGS
}

__global__ __launch_bounds__(256) void heads(const float* __restrict__ sw, const float* __restrict__ sb,
                                             const float* __restrict__ lw, const float* __restrict__ lb,
                                             const int* __restrict__ pih, const int* __restrict__ piw,
                                             float* __restrict__ out){
    __shared__ float fs[32][256];
    __shared__ float ws[54][32];
    int n = blockIdx.y, p0 = blockIdx.x*256, tid = threadIdx.x;
    int p = p0 + tid;
    bool act = p < PP;

    float acc[54];
    #pragma unroll
    for (int j=0;j<54;j++) acc[j] = 0.f;

    const float* fn = g_feat + (size_t)n*CC*PP;
    for (int cc=0; cc<16; cc++){
        __syncthreads();
        #pragma unroll
        for (int r=0;r<32;r++) fs[r][tid] = act ? fn[(size_t)(cc*32+r)*PP + p] : 0.f;
        for (int i=tid; i<54*32; i+=256){
            int j = i >> 5, c = i & 31;
            ws[j][c] = (j < 18) ? sw[j*CC + cc*32 + c] : lw[(j-18)*CC + cc*32 + c];
        }
        __syncthreads();
        #pragma unroll 4
        for (int c=0;c<32;c++){
            float f = fs[c][tid];
            #pragma unroll
            for (int j=0;j<54;j++) acc[j] = fmaf(ws[j][c], f, acc[j]);
        }
    }
    if (!act) return;

    float fih = (float)(*pih), fiw = (float)(*piw);
    size_t lb0 = (size_t)n*PP + p;
    #pragma unroll
    for (int j=0;j<36;j++) out[LOC_OFF + lb0*36 + j] = acc[18+j] + lb[j];
    #pragma unroll
    for (int j=0;j<18;j++) out[SCORE_OFF + lb0*18 + j] = acc[j] + sb[j];

    int y = p / Ww, xx = p - y*Ww;
    float sxc = xx * 16.f, syc = y * 16.f;
    const float RT[3] = {0.5f, 1.f, 2.f};
    const float SC[3] = {8.f, 16.f, 32.f};

    #pragma unroll
    for (int a=0;a<9;a++){
        float r = RT[a/3], s = SC[a - (a/3)*3];
        float bh = 16.f*s*sqrtf(r);
        float bw = 16.f*s*sqrtf(1.f/r);
        float ax1 = sxc + (8.f - bw*0.5f);
        float ay1 = syc + (8.f - bh*0.5f);
        float ax2 = sxc + (8.f + bw*0.5f);
        float ay2 = syc + (8.f + bh*0.5f);

        float l0 = acc[18+a*4+0] + lb[a*4+0];
        float l1 = acc[18+a*4+1] + lb[a*4+1];
        float l2 = acc[18+a*4+2] + lb[a*4+2];
        float l3 = acc[18+a*4+3] + lb[a*4+3];

        float aw = ax2-ax1, ah = ay2-ay1;
        float axc = ax1 + 0.5f*aw, ayc = ay1 + 0.5f*ah;
        float cx = l0*aw + axc, cy = l1*ah + ayc;
        float w2 = expf(l2)*aw, h2 = expf(l3)*ah;
        float x1 = cx - 0.5f*w2, y1 = cy - 0.5f*h2;
        float x2 = cx + 0.5f*w2, y2 = cy + 0.5f*h2;
        x1 = fminf(fmaxf(x1, 0.f), fiw); x2 = fminf(fmaxf(x2, 0.f), fiw);
        y1 = fminf(fmaxf(y1, 0.f), fih); y2 = fminf(fmaxf(y2, 0.f), fih);
        bool valid = ((x2 - x1) >= 16.f) && ((y2 - y1) >= 16.f);

        float s0 = acc[a*2] + sb[a*2], s1 = acc[a*2+1] + sb[a*2+1];
        float m = fmaxf(s0, s1);
        float e0 = expf(s0 - m), e1 = expf(s1 - m);
        float fg = e1 / (e0 + e1);
        float sc = valid ? fg : __int_as_float(0xff800000);

        int ai = p*9 + a;
        size_t bo = (size_t)n*NANCH + ai;
        g_boxes[bo*4+0] = x1; g_boxes[bo*4+1] = y1;
        g_boxes[bo*4+2] = x2; g_boxes[bo*4+3] = y2;
        g_fg[bo] = sc;
        unsigned u = __float_as_uint(sc);
        u = (u & 0x80000000u) ? ~u : (u | 0x80000000u);
        g_keys[((size_t)n << 16) + ai] = ((ull)(~u) << 32) | (unsigned)ai;
    }
}

__global__ void anchors_out(float* __restrict__ out){
    int i = blockIdx.x*blockDim.x + threadIdx.x;
    if (i >= NANCH) return;
    int p = i/9, a = i - p*9;
    int y = p / Ww, xx = p - y*Ww;
    float sxc = xx*16.f, syc = y*16.f;
    const float RT[3] = {0.5f, 1.f, 2.f};
    const float SC[3] = {8.f, 16.f, 32.f};
    float r = RT[a/3], s = SC[a - (a/3)*3];
    float bh = 16.f*s*sqrtf(r);
    float bw = 16.f*s*sqrtf(1.f/r);
    out[ANCH_OFF + i*4+0] = sxc + (8.f - bw*0.5f);
    out[ANCH_OFF + i*4+1] = syc + (8.f - bh*0.5f);
    out[ANCH_OFF + i*4+2] = sxc + (8.f + bw*0.5f);
    out[ANCH_OFF + i*4+3] = syc + (8.f + bh*0.5f);
}

__global__ void pad_keys(){
    int idx = blockIdx.x*blockDim.x + threadIdx.x;
    if (idx >= NIMG*NSORT) return;
    if ((idx & (NSORT-1)) >= NANCH) g_keys[idx] = ~0ull;
}

__global__ __launch_bounds__(512) void presort(){
    __shared__ ull s[4096];
    int n = blockIdx.y, g0 = blockIdx.x*4096, tid = threadIdx.x;
    ull* kb = g_keys + ((size_t)n << 16);
    for (int e=tid; e<4096; e+=512) s[e] = kb[g0+e];
    for (int k=2; k<=4096; k<<=1){
        for (int j=k>>1; j>0; j>>=1){
            __syncthreads();
            for (int t=tid; t<2048; t+=512){
                int i = ((t & ~(j-1)) << 1) | (t & (j-1));
                bool up = (((g0 + i) & k) == 0);
                ull a = s[i], b = s[i+j];
                if ((a > b) == up){ s[i] = b; s[i+j] = a; }
            }
        }
    }
    __syncthreads();
    for (int e=tid; e<4096; e+=512) kb[g0+e] = s[e];
}

__global__ void gstep(int k, int j){
    int idx = blockIdx.x*blockDim.x + threadIdx.x;
    if (idx >= NIMG*(NSORT/2)) return;
    int n = idx >> 15, t = idx & 32767;
    int i = ((t & ~(j-1)) << 1) | (t & (j-1));
    ull* kb = g_keys + ((size_t)n << 16);
    bool up = ((i & k) == 0);
    ull a = kb[i], b = kb[i+j];
    if ((a > b) == up){ kb[i] = b; kb[i+j] = a; }
}

__global__ __launch_bounds__(512) void merge4k(int k){
    __shared__ ull s[4096];
    int n = blockIdx.y, g0 = blockIdx.x*4096, tid = threadIdx.x;
    ull* kb = g_keys + ((size_t)n << 16);
    for (int e=tid; e<4096; e+=512) s[e] = kb[g0+e];
    bool up = ((g0 & k) == 0);
    for (int j=2048; j>0; j>>=1){
        __syncthreads();
        for (int t=tid; t<2048; t+=512){
            int i = ((t & ~(j-1)) << 1) | (t & (j-1));
            ull a = s[i], b = s[i+j];
            if ((a > b) == up){ s[i] = b; s[i+j] = a; }
        }
    }
    __syncthreads();
    for (int e=tid; e<4096; e+=512) kb[g0+e] = s[e];
}

__global__ void gather_top(){
    int idx = blockIdx.x*blockDim.x + threadIdx.x;
    if (idx >= NIMG*PRE) return;
    int n = idx / PRE;
    int r = idx - n*PRE;
    ull key = g_keys[((size_t)n << 16) + r];
    int ai = (int)(key & 0xFFFFFFFFull);
    float4 b = *(const float4*)&g_boxes[((size_t)n*NANCH + ai)*4];
    *(float4*)&g_bsel[(size_t)idx*4] = b;
    g_ssel[idx] = g_fg[(size_t)n*NANCH + ai];
    g_area[idx] = (b.z - b.x) * (b.w - b.y);
}

__global__ void nms_mask(){
    int n = blockIdx.z, rb = blockIdx.y, cb = blockIdx.x;
    int r = rb*64 + threadIdx.x;
    ull* mrow = g_mask + (size_t)n*PRE*NWORD;
    if (cb < rb){
        if (r < PRE) mrow[(size_t)r*NWORD + cb] = 0ull;
        return;
    }
    __shared__ float4 cbx[64];
    __shared__ float  ca[64];
    int j0 = cb*64;
    {
        int j = j0 + threadIdx.x;
        if (j < PRE){
            cbx[threadIdx.x] = *(const float4*)&g_bsel[((size_t)n*PRE + j)*4];
            ca[threadIdx.x]  = g_area[n*PRE + j];
        } else {
            cbx[threadIdx.x] = make_float4(0,0,0,0);
            ca[threadIdx.x] = 0.f;
        }
    }
    __syncthreads();
    if (r >= PRE) return;
    float4 rbx = *(const float4*)&g_bsel[((size_t)n*PRE + r)*4];
    float ra = g_area[n*PRE + r];
    ull bits = 0;
    #pragma unroll 4
    for (int c=0; c<64; c++){
        int j = j0 + c;
        if (j > r && j < PRE){
            float4 q = cbx[c];
            float xx1 = fmaxf(rbx.x, q.x), yy1 = fmaxf(rbx.y, q.y);
            float xx2 = fminf(rbx.z, q.z), yy2 = fminf(rbx.w, q.w);
            float iw_ = fmaxf(xx2 - xx1, 0.f), ih_ = fmaxf(yy2 - yy1, 0.f);
            float inter = iw_ * ih_;
            float iou = inter / (((ra + ca[c]) - inter) + 1e-9f);
            if (iou > 0.7f) bits |= (1ull << c);
        }
    }
    mrow[(size_t)r*NWORD + cb] = bits;
}

__global__ __launch_bounds__(32) void nms_reduce(float* __restrict__ out){
    int n = blockIdx.x;
    int lane = threadIdx.x;
    __shared__ ull remv[NWORD];
    for (int t=lane; t<NWORD; t+=32) remv[t] = 0ull;
    __syncwarp();

    const ull* maskn = g_mask + (size_t)n*PRE*NWORD;
    int nk = 0;
    for (int i=0; i<PRE && nk<POST; i++){
        ull w = remv[i >> 6];
        if (!((w >> (i & 63)) & 1ull)){
            float s = g_ssel[n*PRE + i];
            if (isfinite(s)){
                if (lane < 4)
                    out[ROI_OFF + ((size_t)(n*POST + nk))*4 + lane] =
                        g_bsel[((size_t)n*PRE + i)*4 + lane];
                const ull* row = maskn + (size_t)i*NWORD;
                for (int t=lane; t<NWORD; t+=32) remv[t] |= row[t];
                nk++;
            }
        }
        __syncwarp();
    }
    for (int q = nk*4 + lane; q < POST*4; q += 32)
        out[ROI_OFF + (size_t)n*POST*4 + q] = 0.f;
}

extern "C" void kernel_launch(void* const* d_in, const int* in_sizes, int n_in,
                              void* d_out, int out_size){
    const float* x   = (const float*)d_in[0];
    const float* c1w = (const float*)d_in[1];
    const float* c1b = (const float*)d_in[2];
    const float* sw  = (const float*)d_in[3];
    const float* sb  = (const float*)d_in[4];
    const float* lw  = (const float*)d_in[5];
    const float* lb  = (const float*)d_in[6];
    const int*   ih  = (const int*)d_in[7];
    const int*   iw  = (const int*)d_in[8];
    float* out = (float*)d_out;

    transpose_w<<<(9*CC*CC + 255)/256, 256>>>(c1w);
    conv3x3<<<dim3(30, 4, NIMG), 256>>>(x, c1b);
    heads<<<dim3(15, NIMG), 256>>>(sw, sb, lw, lb, ih, iw, out);
    anchors_out<<<(NANCH + 255)/256, 256>>>(out);
    pad_keys<<<(NIMG*NSORT + 255)/256, 256>>>();

    presort<<<dim3(16, NIMG), 512>>>();
    for (int k = 8192; k <= 65536; k <<= 1){
        for (int j = k >> 1; j >= 4096; j >>= 1)
            gstep<<<(NIMG*(NSORT/2) + 255)/256, 256>>>(k, j);
        merge4k<<<dim3(16, NIMG), 512>>>(k);
    }

    gather_top<<<(NIMG*PRE + 255)/256, 256>>>();
    nms_mask<<<dim3(NWORD, NWORD, NIMG), 64>>>();
    nms_reduce<<<NIMG, 32>>>(out);
}

// round 7
// speedup vs baseline: 1.6319x; 1.6319x over previous
#include <cuda_runtime.h>
#include <cuda_fp16.h>
#include <stdint.h>
#include <math.h>

typedef unsigned long long ull;

#define Hh 50
#define Ww 76
#define PP 3800
#define CC 512
#define NIMG 8
#define NANCH 34200
#define NSORT 65536
#define PRE 6000
#define POST 300
#define NWORD 94

#define LOC_OFF   0
#define SCORE_OFF (NIMG*NANCH*4)
#define ROI_OFF   (SCORE_OFF + NIMG*NANCH*2)
#define ANCH_OFF  (ROI_OFF + NIMG*POST*4)

__device__ float g_feat[(size_t)NIMG*CC*PP];
__device__ __half g_wh[9*CC*CC];
__device__ __half g_wl[9*CC*CC];
__device__ __half g_xh[(size_t)NIMG*PP*CC];
__device__ __half g_xl[(size_t)NIMG*PP*CC];
__device__ float g_boxes[(size_t)NIMG*NANCH*4];
__device__ float g_fg[NIMG*NANCH];
__device__ ull   g_keys[NIMG*NSORT];
__device__ float g_bsel[NIMG*PRE*4];
__device__ float g_ssel[NIMG*PRE];
__device__ float g_area[NIMG*PRE];
__device__ ull   g_mask[(size_t)NIMG*PRE*NWORD];

// ---------------------------------------------------------------- helpers
__device__ __forceinline__ uint32_t smem_u32(const void* p){
    uint32_t a;
    asm("{ .reg .u64 t; cvta.to.shared.u64 t, %1; cvt.u32.u64 %0, t; }" : "=r"(a) : "l"(p));
    return a;
}
__device__ __forceinline__ void cpasync(uint32_t d, const void* s, int sz){
    asm volatile("cp.async.cg.shared.global [%0], [%1], 16, %2;" :: "r"(d), "l"(s), "r"(sz) : "memory");
}
#define LDM4(r, a) \
    asm volatile("ldmatrix.sync.aligned.m8n8.x4.shared.b16 {%0,%1,%2,%3}, [%4];" \
        : "=r"((r)[0]),"=r"((r)[1]),"=r"((r)[2]),"=r"((r)[3]) : "r"(a))
#define MMA(d, a, b0, b1) \
    asm volatile("mma.sync.aligned.m16n8k16.row.col.f32.f16.f16.f32 " \
        "{%0,%1,%2,%3},{%4,%5,%6,%7},{%8,%9},{%0,%1,%2,%3};" \
        : "+f"((d)[0]),"+f"((d)[1]),"+f"((d)[2]),"+f"((d)[3]) \
        : "r"((a)[0]),"r"((a)[1]),"r"((a)[2]),"r"((a)[3]), "r"(b0),"r"(b1))

// stage layout: A_h | A_l | B_h | B_l, each 128 rows x 80B (32 fp16 used)
#define PLSZ 10240
#define STGSZ (4*PLSZ)
#define CONV_SMEM (3*STGSZ)

// ---------------------------------------------------------------- prep: weight split
__global__ void wprep16(const float* __restrict__ w){
    int idx = blockIdx.x*blockDim.x + threadIdx.x;
    if (idx >= 9*CC*CC) return;
    int kk9 = idx >> 18;
    int oc = (idx >> 9) & 511, ic = idx & 511;
    float v = w[((oc<<9) + ic)*9 + kk9];
    __half h = __float2half_rn(v);
    __half l = __float2half_rn((v - __half2float(h)) * 2048.f);
    g_wh[idx] = h; g_wl[idx] = l;
}

// ---------------------------------------------------------------- prep: x split + transpose
__global__ void xsplit(const float* __restrict__ x){
    __shared__ float t[32][33];
    int n = blockIdx.z, p0 = blockIdx.x*32, ic0 = blockIdx.y*32;
    int tx = threadIdx.x, ty = threadIdx.y;   // 32 x 8
    #pragma unroll
    for (int i=0;i<4;i++){
        int ic = ic0 + ty + 8*i, p = p0 + tx;
        t[ty+8*i][tx] = (p < PP) ? x[((size_t)n*CC + ic)*PP + p] : 0.f;
    }
    __syncthreads();
    #pragma unroll
    for (int i=0;i<4;i++){
        int p = p0 + ty + 8*i, ic = ic0 + tx;
        if (p < PP){
            float v = t[tx][ty+8*i];
            __half h = __float2half_rn(v);
            __half l = __float2half_rn((v - __half2float(h)) * 2048.f);
            size_t o = (((size_t)n*PP + p) << 9) + ic;
            g_xh[o] = h; g_xl[o] = l;
        }
    }
}

// ---------------------------------------------------------------- fp16 split HMMA conv
__global__ __launch_bounds__(256,1) void conv_mma(const float* __restrict__ bias){
    extern __shared__ __align__(128) char sm[];
    uint32_t smb = smem_u32(sm);
    const int tid = threadIdx.x, wid = tid >> 5, lane = tid & 31;
    const int n = blockIdx.z, oc0 = blockIdx.y*128, p0 = blockIdx.x*128;
    const int wm32 = (wid >> 1)*32, wn64 = (wid & 1)*64;

    // per-thread fill geometry: row m = tid&127, plane = tid>>7
    const int fm = tid & 127, fpl = tid >> 7;
    const int fp = p0 + fm;
    const int fpy = fp / Ww, fpx = fp - fpy*Ww;

    float accf[2][8][4], accm[2][8][4];
    #pragma unroll
    for (int i=0;i<2;i++)
        #pragma unroll
        for (int j=0;j<8;j++)
            #pragma unroll
            for (int q=0;q<4;q++) accf[i][j][q] = 0.f;

#define ISSUE(CH) {                                                              \
        int kk9 = (CH) >> 4, icc = ((CH) & 15) << 5;                             \
        int dy = kk9/3 - 1, dx = kk9 - (kk9/3)*3 - 1;                            \
        uint32_t sb = smb + ((CH) % 3)*STGSZ;                                    \
        bool av_ = (fp < PP) && ((unsigned)(fpy+dy) < (unsigned)Hh) &&           \
                   ((unsigned)(fpx+dx) < (unsigned)Ww);                          \
        int q_ = av_ ? (fp + dy*Ww + dx) : 0;                                    \
        const __half* as = (fpl ? g_xl : g_xh) + (((size_t)n*PP + q_) << 9) + icc;\
        uint32_t ad = sb + fpl*PLSZ + fm*80;                                     \
        int asz = av_ ? 16 : 0;                                                  \
        cpasync(ad,    as,    asz); cpasync(ad+16, as+8,  asz);                  \
        cpasync(ad+32, as+16, asz); cpasync(ad+48, as+24, asz);                  \
        const __half* bs = (fpl ? g_wl : g_wh) + (((size_t)kk9 << 18) +          \
                           ((size_t)(oc0 + fm) << 9)) + icc;                     \
        uint32_t bd = sb + 2*PLSZ + fpl*PLSZ + fm*80;                            \
        cpasync(bd,    bs,    16); cpasync(bd+16, bs+8,  16);                    \
        cpasync(bd+32, bs+16, 16); cpasync(bd+48, bs+24, 16);                    \
        asm volatile("cp.async.commit_group;" ::: "memory"); }

    ISSUE(0);
    ISSUE(1);

    const int arow = lane & 15;
    const int acolb = (lane >> 4) << 4;   // 0 or 16 bytes

    uint32_t afh[2][2][4], afl[2][2][4], bq[4];

    for (int c = 0; c < 144; c++){
        if (c == 143) asm volatile("cp.async.wait_group 0;" ::: "memory");
        else          asm volatile("cp.async.wait_group 1;" ::: "memory");
        __syncthreads();

        uint32_t Ah = smb + (c % 3)*STGSZ;
        uint32_t Al = Ah + PLSZ, Bh = Ah + 2*PLSZ, Bl = Ah + 3*PLSZ;

        #pragma unroll
        for (int ks=0;ks<2;ks++)
            #pragma unroll
            for (int tm=0;tm<2;tm++){
                uint32_t ro = (wm32 + tm*16 + arow)*80 + ks*32 + acolb;
                LDM4(afh[tm][ks], Ah + ro);
                LDM4(afl[tm][ks], Al + ro);
            }

        // ---- hh ----
        #pragma unroll
        for (int i=0;i<2;i++)
            #pragma unroll
            for (int j=0;j<8;j++)
                #pragma unroll
                for (int q=0;q<4;q++) accm[i][j][q] = 0.f;
        #pragma unroll
        for (int ks=0;ks<2;ks++)
            #pragma unroll
            for (int bt=0;bt<4;bt++){
                LDM4(bq, Bh + (wn64 + bt*16 + arow)*80 + ks*32 + acolb);
                MMA(accm[0][2*bt],   afh[0][ks], bq[0], bq[2]);
                MMA(accm[0][2*bt+1], afh[0][ks], bq[1], bq[3]);
                MMA(accm[1][2*bt],   afh[1][ks], bq[0], bq[2]);
                MMA(accm[1][2*bt+1], afh[1][ks], bq[1], bq[3]);
            }
        #pragma unroll
        for (int i=0;i<2;i++)
            #pragma unroll
            for (int j=0;j<8;j++)
                #pragma unroll
                for (int q=0;q<4;q++) accf[i][j][q] += accm[i][j][q];

        // ---- hl + lh ----
        #pragma unroll
        for (int i=0;i<2;i++)
            #pragma unroll
            for (int j=0;j<8;j++)
                #pragma unroll
                for (int q=0;q<4;q++) accm[i][j][q] = 0.f;
        #pragma unroll
        for (int ks=0;ks<2;ks++)
            #pragma unroll
            for (int bt=0;bt<4;bt++){
                LDM4(bq, Bl + (wn64 + bt*16 + arow)*80 + ks*32 + acolb);
                MMA(accm[0][2*bt],   afh[0][ks], bq[0], bq[2]);
                MMA(accm[0][2*bt+1], afh[0][ks], bq[1], bq[3]);
                MMA(accm[1][2*bt],   afh[1][ks], bq[0], bq[2]);
                MMA(accm[1][2*bt+1], afh[1][ks], bq[1], bq[3]);
                LDM4(bq, Bh + (wn64 + bt*16 + arow)*80 + ks*32 + acolb);
                MMA(accm[0][2*bt],   afl[0][ks], bq[0], bq[2]);
                MMA(accm[0][2*bt+1], afl[0][ks], bq[1], bq[3]);
                MMA(accm[1][2*bt],   afl[1][ks], bq[0], bq[2]);
                MMA(accm[1][2*bt+1], afl[1][ks], bq[1], bq[3]);
            }
        #pragma unroll
        for (int i=0;i<2;i++)
            #pragma unroll
            for (int j=0;j<8;j++)
                #pragma unroll
                for (int q=0;q<4;q++)
                    accf[i][j][q] = fmaf(accm[i][j][q], 4.8828125e-4f, accf[i][j][q]);

        __syncthreads();
        if (c + 2 < 144) ISSUE(c+2);
    }
#undef ISSUE

    // epilogue: regs -> padded smem -> coalesced transposed store
    float* stg = (float*)sm;
    #pragma unroll
    for (int tm=0;tm<2;tm++){
        #pragma unroll
        for (int nt=0;nt<8;nt++){
            int m0 = wm32 + tm*16 + (lane>>2);
            int n0 = wn64 + nt*8 + (lane&3)*2;
            stg[m0*129 + n0]       = accf[tm][nt][0];
            stg[m0*129 + n0 + 1]   = accf[tm][nt][1];
            stg[(m0+8)*129 + n0]   = accf[tm][nt][2];
            stg[(m0+8)*129 + n0+1] = accf[tm][nt][3];
        }
    }
    __syncthreads();

    #pragma unroll 4
    for (int r=0;r<16;r++){
        int oc = wid*16 + r;
        float bsv = bias[oc0 + oc];
        float* dst = g_feat + ((size_t)n*CC + oc0 + oc)*PP + p0;
        #pragma unroll
        for (int q=0;q<4;q++){
            int px = lane + 32*q;
            if (p0 + px < PP) dst[px] = fmaxf(stg[px*129 + oc] + bsv, 0.f);
        }
    }
}

// ---------------------------------------------------------------- heads + proposals
__global__ __launch_bounds__(256) void heads(const float* __restrict__ sw, const float* __restrict__ sb,
                                             const float* __restrict__ lw, const float* __restrict__ lb,
                                             const int* __restrict__ pih, const int* __restrict__ piw,
                                             float* __restrict__ out){
    __shared__ float fs[32][256];
    __shared__ float ws[54][32];
    int n = blockIdx.y, p0 = blockIdx.x*256, tid = threadIdx.x;
    int p = p0 + tid;
    bool act = p < PP;

    float acc[54];
    #pragma unroll
    for (int j=0;j<54;j++) acc[j] = 0.f;

    const float* fn = g_feat + (size_t)n*CC*PP;
    for (int cc=0; cc<16; cc++){
        __syncthreads();
        #pragma unroll
        for (int r=0;r<32;r++) fs[r][tid] = act ? fn[(size_t)(cc*32+r)*PP + p] : 0.f;
        for (int i=tid; i<54*32; i+=256){
            int j = i >> 5, c = i & 31;
            ws[j][c] = (j < 18) ? sw[j*CC + cc*32 + c] : lw[(j-18)*CC + cc*32 + c];
        }
        __syncthreads();
        #pragma unroll 4
        for (int c=0;c<32;c++){
            float f = fs[c][tid];
            #pragma unroll
            for (int j=0;j<54;j++) acc[j] = fmaf(ws[j][c], f, acc[j]);
        }
    }
    if (!act) return;

    float fih = (float)(*pih), fiw = (float)(*piw);
    size_t lb0 = (size_t)n*PP + p;
    #pragma unroll
    for (int j=0;j<36;j++) out[LOC_OFF + lb0*36 + j] = acc[18+j] + lb[j];
    #pragma unroll
    for (int j=0;j<18;j++) out[SCORE_OFF + lb0*18 + j] = acc[j] + sb[j];

    int y = p / Ww, xx = p - y*Ww;
    float sxc = xx * 16.f, syc = y * 16.f;
    const float RT[3] = {0.5f, 1.f, 2.f};
    const float SC[3] = {8.f, 16.f, 32.f};

    #pragma unroll
    for (int a=0;a<9;a++){
        float r = RT[a/3], s = SC[a - (a/3)*3];
        float bh = 16.f*s*sqrtf(r);
        float bw = 16.f*s*sqrtf(1.f/r);
        float ax1 = sxc + (8.f - bw*0.5f);
        float ay1 = syc + (8.f - bh*0.5f);
        float ax2 = sxc + (8.f + bw*0.5f);
        float ay2 = syc + (8.f + bh*0.5f);

        float l0 = acc[18+a*4+0] + lb[a*4+0];
        float l1 = acc[18+a*4+1] + lb[a*4+1];
        float l2 = acc[18+a*4+2] + lb[a*4+2];
        float l3 = acc[18+a*4+3] + lb[a*4+3];

        float aw = ax2-ax1, ah = ay2-ay1;
        float axc = ax1 + 0.5f*aw, ayc = ay1 + 0.5f*ah;
        float cx = l0*aw + axc, cy = l1*ah + ayc;
        float w2 = expf(l2)*aw, h2 = expf(l3)*ah;
        float x1 = cx - 0.5f*w2, y1 = cy - 0.5f*h2;
        float x2 = cx + 0.5f*w2, y2 = cy + 0.5f*h2;
        x1 = fminf(fmaxf(x1, 0.f), fiw); x2 = fminf(fmaxf(x2, 0.f), fiw);
        y1 = fminf(fmaxf(y1, 0.f), fih); y2 = fminf(fmaxf(y2, 0.f), fih);
        bool valid = ((x2 - x1) >= 16.f) && ((y2 - y1) >= 16.f);

        float s0 = acc[a*2] + sb[a*2], s1 = acc[a*2+1] + sb[a*2+1];
        float m = fmaxf(s0, s1);
        float e0 = expf(s0 - m), e1 = expf(s1 - m);
        float fg = e1 / (e0 + e1);
        float sc = valid ? fg : __int_as_float(0xff800000);

        int ai = p*9 + a;
        size_t bo = (size_t)n*NANCH + ai;
        g_boxes[bo*4+0] = x1; g_boxes[bo*4+1] = y1;
        g_boxes[bo*4+2] = x2; g_boxes[bo*4+3] = y2;
        g_fg[bo] = sc;
        unsigned u = __float_as_uint(sc);
        u = (u & 0x80000000u) ? ~u : (u | 0x80000000u);
        g_keys[((size_t)n << 16) + ai] = ((ull)(~u) << 32) | (unsigned)ai;
    }
}

__global__ void anchors_out(float* __restrict__ out){
    int i = blockIdx.x*blockDim.x + threadIdx.x;
    if (i >= NANCH) return;
    int p = i/9, a = i - p*9;
    int y = p / Ww, xx = p - y*Ww;
    float sxc = xx*16.f, syc = y*16.f;
    const float RT[3] = {0.5f, 1.f, 2.f};
    const float SC[3] = {8.f, 16.f, 32.f};
    float r = RT[a/3], s = SC[a - (a/3)*3];
    float bh = 16.f*s*sqrtf(r);
    float bw = 16.f*s*sqrtf(1.f/r);
    out[ANCH_OFF + i*4+0] = sxc + (8.f - bw*0.5f);
    out[ANCH_OFF + i*4+1] = syc + (8.f - bh*0.5f);
    out[ANCH_OFF + i*4+2] = sxc + (8.f + bw*0.5f);
    out[ANCH_OFF + i*4+3] = syc + (8.f + bh*0.5f);
}

__global__ void pad_keys(){
    int idx = blockIdx.x*blockDim.x + threadIdx.x;
    if (idx >= NIMG*NSORT) return;
    if ((idx & (NSORT-1)) >= NANCH) g_keys[idx] = ~0ull;
}

__global__ __launch_bounds__(512) void presort(){
    __shared__ ull s[4096];
    int n = blockIdx.y, g0 = blockIdx.x*4096, tid = threadIdx.x;
    ull* kb = g_keys + ((size_t)n << 16);
    for (int e=tid; e<4096; e+=512) s[e] = kb[g0+e];
    for (int k=2; k<=4096; k<<=1){
        for (int j=k>>1; j>0; j>>=1){
            __syncthreads();
            for (int t=tid; t<2048; t+=512){
                int i = ((t & ~(j-1)) << 1) | (t & (j-1));
                bool up = (((g0 + i) & k) == 0);
                ull a = s[i], b = s[i+j];
                if ((a > b) == up){ s[i] = b; s[i+j] = a; }
            }
        }
    }
    __syncthreads();
    for (int e=tid; e<4096; e+=512) kb[g0+e] = s[e];
}

__global__ void gstep(int k, int j){
    int idx = blockIdx.x*blockDim.x + threadIdx.x;
    if (idx >= NIMG*(NSORT/2)) return;
    int n = idx >> 15, t = idx & 32767;
    int i = ((t & ~(j-1)) << 1) | (t & (j-1));
    ull* kb = g_keys + ((size_t)n << 16);
    bool up = ((i & k) == 0);
    ull a = kb[i], b = kb[i+j];
    if ((a > b) == up){ kb[i] = b; kb[i+j] = a; }
}

__global__ __launch_bounds__(512) void merge4k(int k){
    __shared__ ull s[4096];
    int n = blockIdx.y, g0 = blockIdx.x*4096, tid = threadIdx.x;
    ull* kb = g_keys + ((size_t)n << 16);
    for (int e=tid; e<4096; e+=512) s[e] = kb[g0+e];
    bool up = ((g0 & k) == 0);
    for (int j=2048; j>0; j>>=1){
        __syncthreads();
        for (int t=tid; t<2048; t+=512){
            int i = ((t & ~(j-1)) << 1) | (t & (j-1));
            ull a = s[i], b = s[i+j];
            if ((a > b) == up){ s[i] = b; s[i+j] = a; }
        }
    }
    __syncthreads();
    for (int e=tid; e<4096; e+=512) kb[g0+e] = s[e];
}

__global__ void gather_top(){
    int idx = blockIdx.x*blockDim.x + threadIdx.x;
    if (idx >= NIMG*PRE) return;
    int n = idx / PRE;
    int r = idx - n*PRE;
    ull key = g_keys[((size_t)n << 16) + r];
    int ai = (int)(key & 0xFFFFFFFFull);
    float4 b = *(const float4*)&g_boxes[((size_t)n*NANCH + ai)*4];
    *(float4*)&g_bsel[(size_t)idx*4] = b;
    g_ssel[idx] = g_fg[(size_t)n*NANCH + ai];
    g_area[idx] = (b.z - b.x) * (b.w - b.y);
}

__global__ void nms_mask(){
    int n = blockIdx.z, rb = blockIdx.y, cb = blockIdx.x;
    int r = rb*64 + threadIdx.x;
    ull* mrow = g_mask + (size_t)n*PRE*NWORD;
    if (cb < rb){
        if (r < PRE) mrow[(size_t)r*NWORD + cb] = 0ull;
        return;
    }
    __shared__ float4 cbx[64];
    __shared__ float  ca[64];
    int j0 = cb*64;
    {
        int j = j0 + threadIdx.x;
        if (j < PRE){
            cbx[threadIdx.x] = *(const float4*)&g_bsel[((size_t)n*PRE + j)*4];
            ca[threadIdx.x]  = g_area[n*PRE + j];
        } else {
            cbx[threadIdx.x] = make_float4(0,0,0,0);
            ca[threadIdx.x] = 0.f;
        }
    }
    __syncthreads();
    if (r >= PRE) return;
    float4 rbx = *(const float4*)&g_bsel[((size_t)n*PRE + r)*4];
    float ra = g_area[n*PRE + r];
    ull bits = 0;
    #pragma unroll 4
    for (int c=0; c<64; c++){
        int j = j0 + c;
        if (j > r && j < PRE){
            float4 q = cbx[c];
            float xx1 = fmaxf(rbx.x, q.x), yy1 = fmaxf(rbx.y, q.y);
            float xx2 = fminf(rbx.z, q.z), yy2 = fminf(rbx.w, q.w);
            float iw_ = fmaxf(xx2 - xx1, 0.f), ih_ = fmaxf(yy2 - yy1, 0.f);
            float inter = iw_ * ih_;
            float iou = inter / (((ra + ca[c]) - inter) + 1e-9f);
            if (iou > 0.7f) bits |= (1ull << c);
        }
    }
    mrow[(size_t)r*NWORD + cb] = bits;
}

__global__ __launch_bounds__(32) void nms_reduce(float* __restrict__ out){
    int n = blockIdx.x;
    int lane = threadIdx.x;
    __shared__ ull remv[NWORD];
    for (int t=lane; t<NWORD; t+=32) remv[t] = 0ull;
    __syncwarp();

    const ull* maskn = g_mask + (size_t)n*PRE*NWORD;
    int nk = 0;
    for (int i=0; i<PRE && nk<POST; i++){
        ull w = remv[i >> 6];
        if (!((w >> (i & 63)) & 1ull)){
            float s = g_ssel[n*PRE + i];
            if (isfinite(s)){
                if (lane < 4)
                    out[ROI_OFF + ((size_t)(n*POST + nk))*4 + lane] =
                        g_bsel[((size_t)n*PRE + i)*4 + lane];
                const ull* row = maskn + (size_t)i*NWORD;
                for (int t=lane; t<NWORD; t+=32) remv[t] |= row[t];
                nk++;
            }
        }
        __syncwarp();
    }
    for (int q = nk*4 + lane; q < POST*4; q += 32)
        out[ROI_OFF + (size_t)n*POST*4 + q] = 0.f;
}

extern "C" void kernel_launch(void* const* d_in, const int* in_sizes, int n_in,
                              void* d_out, int out_size){
    const float* x   = (const float*)d_in[0];
    const float* c1w = (const float*)d_in[1];
    const float* c1b = (const float*)d_in[2];
    const float* sw  = (const float*)d_in[3];
    const float* sb  = (const float*)d_in[4];
    const float* lw  = (const float*)d_in[5];
    const float* lb  = (const float*)d_in[6];
    const int*   ih  = (const int*)d_in[7];
    const int*   iw  = (const int*)d_in[8];
    float* out = (float*)d_out;

    cudaFuncSetAttribute(conv_mma, cudaFuncAttributeMaxDynamicSharedMemorySize, CONV_SMEM);

    wprep16<<<(9*CC*CC + 255)/256, 256>>>(c1w);
    xsplit<<<dim3((PP+31)/32, CC/32, NIMG), dim3(32,8)>>>(x);
    conv_mma<<<dim3(30, 4, NIMG), 256, CONV_SMEM>>>(c1b);
    heads<<<dim3(15, NIMG), 256>>>(sw, sb, lw, lb, ih, iw, out);
    anchors_out<<<(NANCH + 255)/256, 256>>>(out);
    pad_keys<<<(NIMG*NSORT + 255)/256, 256>>>();

    presort<<<dim3(16, NIMG), 512>>>();
    for (int k = 8192; k <= 65536; k <<= 1){
        for (int j = k >> 1; j >= 4096; j >>= 1)
            gstep<<<(NIMG*(NSORT/2) + 255)/256, 256>>>(k, j);
        merge4k<<<dim3(16, NIMG), 512>>>(k);
    }

    gather_top<<<(NIMG*PRE + 255)/256, 256>>>();
    nms_mask<<<dim3(NWORD, NWORD, NIMG), 64>>>();
    nms_reduce<<<NIMG, 32>>>(out);
}